// round 10
// baseline (speedup 1.0000x reference)
#include <cuda_runtime.h>
#include <cuda_bf16.h>
#include <cstdint>
#include <cmath>

#define NT 448                 // 14 warps per CTA, grid=147, one wave
#define DTC 0.0166667f
#define NNR 0.3f

// ---- smem layout (u32 units) ----
#define WB_O   0               // bf16x2 weight frags, 4 "layers" (3 MLP + w4): 16384
#define BS_O   16384           // fp32 [m][2][32] biases b2,b3
#define B4_O   16896           // fp32 [8]
#define PAR_O  16904           // fp32 [8][8]
#define ALS_O  16968           // fp32 [8][448] staged+clipped activations
#define SMEM_U 20552
#define SMEM_BYTES (SMEM_U*4)

__device__ __forceinline__ int widx(int m, int l, int ks, int kh, int o, int tig) {
    return ((((m * 4 + l) * 2 + ks) * 2 + kh) * 32 + o) * 4 + tig;
}

#define CVT_BF16X2(res, a, b) \
    asm("cvt.rn.bf16x2.f32 %0, %1, %2;" : "=r"(res) : "f"(b), "f"(a))

__device__ __forceinline__ void mma16816(float* d, const uint32_t* a, uint32_t b0, uint32_t b1) {
    asm volatile("mma.sync.aligned.m16n8k16.row.col.f32.bf16.bf16.f32 "
                 "{%0,%1,%2,%3}, {%4,%5,%6,%7}, {%8,%9}, {%0,%1,%2,%3};"
                 : "+f"(d[0]), "+f"(d[1]), "+f"(d[2]), "+f"(d[3])
                 : "r"(a[0]), "r"(a[1]), "r"(a[2]), "r"(a[3]), "r"(b0), "r"(b1));
}

__device__ __forceinline__ float tanh_ap(float x) {
    float y; asm("tanh.approx.f32 %0, %1;" : "=f"(y) : "f"(x)); return y;
}
__device__ __forceinline__ float leakys(float x) {
    return fmaf(0.505f, x, 0.495f * fabsf(x));
}

// closed-form 2x2 expm + phi1 solve (validated R1-R9)
__device__ __forceinline__ void finalize(float Ks, float Bs, float s0, float s1,
                                         float Iv, float invI, float Bv, float Kv,
                                         float& o0, float& o1) {
    float A10 = -(Ks + Kv) * invI;
    float Dd  = 2.0f * sqrtf(fmaxf(Ks * Iv, 0.0f));
    float A11 = -(Dd + Bv) * invI;
    float B10 = Bs * invI;
    float a10 = A10 * DTC, a11 = A11 * DTC;
    float s = 0.5f * a11;
    float q = fmaf(s, s, DTC * a10);
    float c, kf;
    if (q >= 0.0f) {
        float w = sqrtf(q);
        c = coshf(w);
        kf = (w > 1e-4f) ? sinhf(w) / w : 1.0f + q * (1.0f / 6.0f);
    } else {
        float w = sqrtf(-q);
        c = __cosf(w);
        kf = (w > 1e-4f) ? __sinf(w) / w : 1.0f + q * (1.0f / 6.0f);
    }
    float es = __expf(s);
    float g  = es * fmaf(-s, kf, c);
    float kk = es * kf;
    float Ad01 = kk * DTC;
    float Ad10 = kk * a10;
    float Ad11 = g + kk * a11;
    float v  = DTC * B10;
    float y1 = kk * v;
    float r1 = (Ad11 - 1.0f) * v;
    float y0 = (r1 - a11 * y1) / a10;
    o0 = fmaf(g,    s0, fmaf(Ad01, s1, y0));
    o1 = fmaf(Ad10, s0, fmaf(Ad11, s1, y1));
}

__global__ __launch_bounds__(NT, 1)
void joint_mma(const float* __restrict__ SS,  const float* __restrict__ AL,
               const float* __restrict__ K0,  const float* __restrict__ K1,
               const float* __restrict__ L0,  const float* __restrict__ L1,
               const float* __restrict__ Ms,  const float* __restrict__ Ip,
               const float* __restrict__ Bvp, const float* __restrict__ Kvp,
               const float* __restrict__ W1,  const float* __restrict__ b1,
               const float* __restrict__ W2,  const float* __restrict__ b2,
               const float* __restrict__ W3,  const float* __restrict__ b3,
               const float* __restrict__ W4,  const float* __restrict__ b4,
               float* __restrict__ out, int B) {
    extern __shared__ uint32_t smu[];
    float* smf = reinterpret_cast<float*>(smu);
    const int tid = threadIdx.x;

    // ---- stage weight fragments (bf16x2, mma B-fragment order); b1 folded into W1 row 3;
    //      "layer 3" slot holds W4 in N-col 0 ----
    for (int t = tid; t < 16384; t += NT) {
        int m  = t / 2048;  int r = t - m * 2048;
        int l  = r / 512;   r -= l * 512;
        int ks = r / 256;   r -= ks * 256;
        int kh = r / 128;   r -= kh * 128;
        int o  = r >> 2;    int tg = r & 3;
        int i0 = ks * 16 + kh * 8 + tg * 2;
        float v0 = 0.0f, v1 = 0.0f;
        if (l == 0) {
            if (i0 < 3)      v0 = W1[(m * 32 + o) * 3 + i0];
            if (i0 + 1 < 3)  v1 = W1[(m * 32 + o) * 3 + i0 + 1];
            else if (i0 + 1 == 3) v1 = b1[m * 32 + o];          // bias via x[3]=1
        } else if (l <= 2) {
            const float* W = (l == 1) ? W2 : W3;
            v0 = W[(m * 32 + o) * 32 + i0];
            v1 = W[(m * 32 + o) * 32 + i0 + 1];
        } else if (o == 0) {                                    // w4 as B col 0
            v0 = W4[m * 32 + i0];
            v1 = W4[m * 32 + i0 + 1];
        }
        uint32_t pk; CVT_BF16X2(pk, v0, v1);
        smu[WB_O + t] = pk;
    }
    for (int t = tid; t < 512; t += NT) {                        // b2, b3
        int m = t >> 6, li = (t >> 5) & 1, o = t & 31;
        smf[BS_O + t] = (li ? b3 : b2)[m * 32 + o];
    }
    if (tid < 8) {
        smf[B4_O + tid] = b4[tid];
        float ms = Ms[tid];
        float* p = smf + PAR_O + tid * 8;
        p[0] = K0[tid]; p[1] = K1[tid]; p[2] = L0[tid]; p[3] = L1[tid];
        p[4] = ms; p[5] = ms * ms; p[6] = K1[tid] * L1[tid];
    }
    // ---- stage AL (coalesced, clipped) into smem [m][448] ----
    for (int t = tid; t < 3584; t += NT) {
        int le = t >> 3, m = t & 7;
        int ge = blockIdx.x * NT + le;
        if (ge >= B) ge = B - 1;
        smf[ALS_O + m * NT + le] = fminf(fmaxf(AL[(size_t)ge * 8 + m], 0.0f), 1.0f);
    }
    __syncthreads();

    const int lane = tid & 31, wid = tid >> 5;
    const int g = lane >> 2, tig = lane & 3;
    const int cb = 2 * tig;
    const float Iv = __ldg(Ip), Bv = __ldg(Bvp), Kv = __ldg(Kvp);
    const float invI = 1.0f / Iv;
    const float2* SS2 = reinterpret_cast<const float2*>(SS);
    float2* seg2 = reinterpret_cast<float2*>(out + B);

    const int le0 = wid * 32 + g;             // local element of q=0
    int e[4];
    e[0] = blockIdx.x * NT + le0;
    e[1] = e[0] + 8;
    e[2] = e[0] + 16;
    e[3] = e[0] + 24;
#pragma unroll
    for (int q = 0; q < 4; q++) if (e[q] >= B) e[q] = B - 1;

    float2 ss[4];
#pragma unroll
    for (int q = 0; q < 4; q++) ss[q] = SS2[e[q]];
    float Ks[4] = {0.f, 0.f, 0.f, 0.f};
    float Bs[4] = {0.f, 0.f, 0.f, 0.f};

#pragma unroll 1
    for (int m = 0; m < 8; m++) {
        const float* par = smf + PAR_O + m * 8;
        const float Msv = par[4];
        const float* als = smf + ALS_O + m * NT + le0;
        float a[4], lv[4];
        a[0] = als[0]; a[1] = als[8]; a[2] = als[16]; a[3] = als[24];
#pragma unroll
        for (int q = 0; q < 4; q++) lv[q] = ss[q].x * Msv;

        // ---- layer 1 (x = [l, dl, a, 1, 0...], b1 folded) ----
        float D[2][4][4];
        {
            uint32_t A0[2][4];
#pragma unroll
            for (int ch = 0; ch < 2; ch++) {
                uint32_t r0 = 0, r1 = 0;
                if (tig == 0) {
                    CVT_BF16X2(r0, lv[ch*2],   ss[ch*2].y   * Msv);
                    CVT_BF16X2(r1, lv[ch*2+1], ss[ch*2+1].y * Msv);
                } else if (tig == 1) {
                    CVT_BF16X2(r0, a[ch*2],   1.0f);
                    CVT_BF16X2(r1, a[ch*2+1], 1.0f);
                }
                A0[ch][0] = r0; A0[ch][1] = r1; A0[ch][2] = 0u; A0[ch][3] = 0u;
            }
#pragma unroll
            for (int t4 = 0; t4 < 4; t4++) {
                uint32_t bb0 = smu[WB_O + widx(m, 0, 0, 0, t4 * 8 + g, tig)];
                uint32_t bb1 = smu[WB_O + widx(m, 0, 0, 1, t4 * 8 + g, tig)];
#pragma unroll
                for (int ch = 0; ch < 2; ch++) {
#pragma unroll
                    for (int i = 0; i < 4; i++) D[ch][t4][i] = 0.0f;
                    mma16816(D[ch][t4], A0[ch], bb0, bb1);
                }
            }
        }

        // ---- transitions: epi (optional bias + leaky + cvt) -> K=32 mma into layer l+1 ----
        uint32_t Ak0[2][4], Ak1[2][4];
#pragma unroll 1
        for (int l = 1; l <= 3; l++) {
            const float* bb = (l == 1) ? nullptr : smf + BS_O + (m * 2 + (l - 2)) * 32 + cb;
#pragma unroll
            for (int t4 = 0; t4 < 4; t4++) {
                float bx = 0.f, by = 0.f;
                if (l > 1) { float2 bp = *reinterpret_cast<const float2*>(bb + t4 * 8); bx = bp.x; by = bp.y; }
#pragma unroll
                for (int ch = 0; ch < 2; ch++) {
                    float h0 = leakys(D[ch][t4][0] + bx);
                    float h1 = leakys(D[ch][t4][1] + by);
                    float h2 = leakys(D[ch][t4][2] + bx);
                    float h3 = leakys(D[ch][t4][3] + by);
                    uint32_t r01, r23;
                    CVT_BF16X2(r01, h0, h1);
                    CVT_BF16X2(r23, h2, h3);
                    if      (t4 == 0) { Ak0[ch][0] = r01; Ak0[ch][1] = r23; }
                    else if (t4 == 1) { Ak0[ch][2] = r01; Ak0[ch][3] = r23; }
                    else if (t4 == 2) { Ak1[ch][0] = r01; Ak1[ch][1] = r23; }
                    else              { Ak1[ch][2] = r01; Ak1[ch][3] = r23; }
                }
            }
            if (l < 3) {
#pragma unroll
                for (int t4 = 0; t4 < 4; t4++) {
                    uint32_t b00 = smu[WB_O + widx(m, l, 0, 0, t4 * 8 + g, tig)];
                    uint32_t b01 = smu[WB_O + widx(m, l, 0, 1, t4 * 8 + g, tig)];
                    uint32_t b10 = smu[WB_O + widx(m, l, 1, 0, t4 * 8 + g, tig)];
                    uint32_t b11 = smu[WB_O + widx(m, l, 1, 1, t4 * 8 + g, tig)];
#pragma unroll
                    for (int ch = 0; ch < 2; ch++) {
#pragma unroll
                        for (int i = 0; i < 4; i++) D[ch][t4][i] = 0.0f;
                        mma16816(D[ch][t4], Ak0[ch], b00, b01);
                        mma16816(D[ch][t4], Ak1[ch], b10, b11);
                    }
                }
            }
        }

        // ---- layer 4 via mma: w4 in B col 0 (N=8 tile) ----
        float D4[2][4];
        {
            uint32_t b00 = smu[WB_O + widx(m, 3, 0, 0, g, tig)];
            uint32_t b01 = smu[WB_O + widx(m, 3, 0, 1, g, tig)];
            uint32_t b10 = smu[WB_O + widx(m, 3, 1, 0, g, tig)];
            uint32_t b11 = smu[WB_O + widx(m, 3, 1, 1, g, tig)];
#pragma unroll
            for (int ch = 0; ch < 2; ch++) {
#pragma unroll
                for (int i = 0; i < 4; i++) D4[ch][i] = 0.0f;
                mma16816(D4[ch], Ak0[ch], b00, b01);
                mma16816(D4[ch], Ak1[ch], b10, b11);
            }
        }

        // ---- tanh + muscle epilogue (results live on tig==0: cols 0/1) ----
        if (tig == 0) {
            const float b4v = smf[B4_O + m];
            const float K0v = par[0], K1v = par[1], L0v = par[2], L1v = par[3];
            const float Ms2v = par[5], K1L1v = par[6];
            float s[4] = { D4[0][0], D4[0][2], D4[1][0], D4[1][2] };
#pragma unroll
            for (int q = 0; q < 4; q++) {
                float nn = NNR * tanh_ap(s[q] + b4v);
                float K = fmaf(a[q], K1v, K0v);
                Ks[q] = fmaf(K, Ms2v, Ks[q]);
                float tL = fmaf(a[q], L1v, L0v) - fabsf(lv[q]);
                float BF = fmaf(a[q] * a[q] * nn, K1L1v, K * tL);
                Bs[q] = fmaf(BF, Msv, Bs[q]);
            }
        }
    }

    // ---- expm epilogue + stores (one lane per quad) ----
    if (tig == 0) {
#pragma unroll
        for (int q = 0; q < 4; q++) {
            float o0, o1;
            finalize(Ks[q], Bs[q], ss[q].x, ss[q].y, Iv, invI, Bv, Kv, o0, o1);
            out[e[q]]  = o0;
            seg2[e[q]] = make_float2(o0, o1);
        }
    }
}

extern "C" void kernel_launch(void* const* d_in, const int* in_sizes, int n_in,
                              void* d_out, int out_size) {
    const float* SS  = (const float*)d_in[0];
    const float* AL  = (const float*)d_in[1];
    const float* K0  = (const float*)d_in[2];
    const float* K1  = (const float*)d_in[3];
    const float* L0  = (const float*)d_in[4];
    const float* L1  = (const float*)d_in[5];
    const float* Ms  = (const float*)d_in[6];
    const float* Ip  = (const float*)d_in[7];
    const float* Bv  = (const float*)d_in[8];
    const float* Kv  = (const float*)d_in[9];
    const float* W1  = (const float*)d_in[10];
    const float* b1  = (const float*)d_in[11];
    const float* W2  = (const float*)d_in[12];
    const float* b2  = (const float*)d_in[13];
    const float* W3  = (const float*)d_in[14];
    const float* b3  = (const float*)d_in[15];
    const float* W4  = (const float*)d_in[16];
    const float* b4  = (const float*)d_in[17];
    float* out = (float*)d_out;

    const int B = in_sizes[0] / 2;
    const int grid = (B + NT - 1) / NT;

    cudaFuncSetAttribute(joint_mma, cudaFuncAttributeMaxDynamicSharedMemorySize, SMEM_BYTES);
    joint_mma<<<grid, NT, SMEM_BYTES>>>(SS, AL, K0, K1, L0, L1, Ms, Ip, Bv, Kv,
                                        W1, b1, W2, b2, W3, b3, W4, b4, out, B);
}

// round 11
// speedup vs baseline: 1.1509x; 1.1509x over previous
#include <cuda_runtime.h>
#include <cuda_bf16.h>
#include <cstdint>
#include <cmath>

#define NT 448                 // 14 warps per CTA, grid=147, one wave
#define DTC 0.0166667f
#define NNR 0.3f

// ---- smem layout (u32 units) ----
#define WB_O   0               // bf16x2 weight frags: ((((m*3+l)*2+ks)*2+kh)*32+o)*4+tig
#define BS2_O  12288           // bf16x2 b2 pairs [8][16]
#define B3_O   12416           // fp32 [8][32]
#define W4_O   12672           // fp32 [8][32]
#define B4_O   12928           // fp32 [8]
#define PAR_O  12936           // fp32 [8][8]
#define ALS_O  13000           // fp32 [8][449] staged+clipped activations (padded stride)
#define ALSP   449
#define SMEM_U (ALS_O + 8*ALSP)
#define SMEM_BYTES (SMEM_U*4)

__device__ __forceinline__ int widx(int m, int l, int ks, int kh, int o, int tig) {
    return ((((m * 3 + l) * 2 + ks) * 2 + kh) * 32 + o) * 4 + tig;
}

#define CVT_BF16X2(res, a, b) \
    asm("cvt.rn.bf16x2.f32 %0, %1, %2;" : "=r"(res) : "f"(b), "f"(a))
#define HADD2(res, a, b) \
    asm("add.rn.bf16x2 %0, %1, %2;" : "=r"(res) : "r"(a), "r"(b))
#define HMUL2(res, a, b) \
    asm("mul.rn.bf16x2 %0, %1, %2;" : "=r"(res) : "r"(a), "r"(b))
#define HMAX2(res, a, b) \
    asm("max.bf16x2 %0, %1, %2;" : "=r"(res) : "r"(a), "r"(b))

__device__ __forceinline__ void mma16816(float* d, const uint32_t* a, uint32_t b0, uint32_t b1) {
    asm volatile("mma.sync.aligned.m16n8k16.row.col.f32.bf16.bf16.f32 "
                 "{%0,%1,%2,%3}, {%4,%5,%6,%7}, {%8,%9}, {%0,%1,%2,%3};"
                 : "+f"(d[0]), "+f"(d[1]), "+f"(d[2]), "+f"(d[3])
                 : "r"(a[0]), "r"(a[1]), "r"(a[2]), "r"(a[3]), "r"(b0), "r"(b1));
}

__device__ __forceinline__ float tanh_ap(float x) {
    float y; asm("tanh.approx.f32 %0, %1;" : "=f"(y) : "f"(x)); return y;
}
__device__ __forceinline__ float leakys(float x) {
    return fmaxf(x, 0.01f * x);
}

// closed-form 2x2 expm + phi1 solve (validated R1-R10)
__device__ __forceinline__ void finalize(float Ks, float Bs, float s0, float s1,
                                         float Iv, float invI, float Bv, float Kv,
                                         float& o0, float& o1) {
    float A10 = -(Ks + Kv) * invI;
    float Dd  = 2.0f * sqrtf(fmaxf(Ks * Iv, 0.0f));
    float A11 = -(Dd + Bv) * invI;
    float B10 = Bs * invI;
    float a10 = A10 * DTC, a11 = A11 * DTC;
    float s = 0.5f * a11;
    float q = fmaf(s, s, DTC * a10);
    float c, kf;
    if (q >= 0.0f) {
        float w = sqrtf(q);
        c = coshf(w);
        kf = (w > 1e-4f) ? sinhf(w) / w : 1.0f + q * (1.0f / 6.0f);
    } else {
        float w = sqrtf(-q);
        c = __cosf(w);
        kf = (w > 1e-4f) ? __sinf(w) / w : 1.0f + q * (1.0f / 6.0f);
    }
    float es = __expf(s);
    float g  = es * fmaf(-s, kf, c);
    float kk = es * kf;
    float Ad01 = kk * DTC;
    float Ad10 = kk * a10;
    float Ad11 = g + kk * a11;
    float v  = DTC * B10;
    float y1 = kk * v;
    float r1 = (Ad11 - 1.0f) * v;
    float y0 = (r1 - a11 * y1) / a10;
    o0 = fmaf(g,    s0, fmaf(Ad01, s1, y0));
    o1 = fmaf(Ad10, s0, fmaf(Ad11, s1, y1));
}

__global__ __launch_bounds__(NT, 1)
void joint_mma(const float* __restrict__ SS,  const float* __restrict__ AL,
               const float* __restrict__ K0,  const float* __restrict__ K1,
               const float* __restrict__ L0,  const float* __restrict__ L1,
               const float* __restrict__ Ms,  const float* __restrict__ Ip,
               const float* __restrict__ Bvp, const float* __restrict__ Kvp,
               const float* __restrict__ W1,  const float* __restrict__ b1,
               const float* __restrict__ W2,  const float* __restrict__ b2,
               const float* __restrict__ W3,  const float* __restrict__ b3,
               const float* __restrict__ W4,  const float* __restrict__ b4,
               float* __restrict__ out, int B) {
    extern __shared__ uint32_t smu[];
    float* smf = reinterpret_cast<float*>(smu);
    const int tid = threadIdx.x;

    // ---- weight frags (b1 folded into W1 row 3 via x[3]=1) ----
    for (int t = tid; t < 12288; t += NT) {
        int m  = t / 1536;  int r = t - m * 1536;
        int l  = r / 512;   r -= l * 512;
        int ks = r / 256;   r -= ks * 256;
        int kh = r / 128;   r -= kh * 128;
        int o  = r >> 2;    int tg = r & 3;
        int i0 = ks * 16 + kh * 8 + tg * 2;
        float v0 = 0.0f, v1 = 0.0f;
        if (l == 0) {
            if (i0 < 3)      v0 = W1[(m * 32 + o) * 3 + i0];
            if (i0 + 1 < 3)  v1 = W1[(m * 32 + o) * 3 + i0 + 1];
            else if (i0 + 1 == 3) v1 = b1[m * 32 + o];
        } else {
            const float* W = (l == 1) ? W2 : W3;
            v0 = W[(m * 32 + o) * 32 + i0];
            v1 = W[(m * 32 + o) * 32 + i0 + 1];
        }
        uint32_t pk; CVT_BF16X2(pk, v0, v1);
        smu[WB_O + t] = pk;
    }
    for (int t = tid; t < 128; t += NT) {                    // b2 as bf16x2 pairs
        int m = t >> 4, p = t & 15;
        uint32_t pk; CVT_BF16X2(pk, b2[m * 32 + 2 * p], b2[m * 32 + 2 * p + 1]);
        smu[BS2_O + t] = pk;
    }
    for (int t = tid; t < 256; t += NT) {                    // b3, w4 fp32
        smf[B3_O + t] = b3[t];
        smf[W4_O + t] = W4[t];
    }
    if (tid < 8) {
        smf[B4_O + tid] = b4[tid];
        float ms = Ms[tid];
        float* p = smf + PAR_O + tid * 8;
        p[0] = K0[tid]; p[1] = K1[tid]; p[2] = L0[tid]; p[3] = L1[tid];
        p[4] = ms; p[5] = ms * ms; p[6] = K1[tid] * L1[tid];
    }
    // ---- stage AL (coalesced, clipped) ----
    for (int t = tid; t < 3584; t += NT) {
        int le = t >> 3, m = t & 7;
        int ge = blockIdx.x * NT + le;
        if (ge >= B) ge = B - 1;
        smf[ALS_O + m * ALSP + le] = fminf(fmaxf(AL[(size_t)ge * 8 + m], 0.0f), 1.0f);
    }
    __syncthreads();

    const int lane = tid & 31, wid = tid >> 5;
    const int g = lane >> 2, tig = lane & 3;
    const int cb = 2 * tig;
    const float Iv = __ldg(Ip), Bv = __ldg(Bvp), Kv = __ldg(Kvp);
    const float invI = 1.0f / Iv;
    const float2* SS2 = reinterpret_cast<const float2*>(SS);
    float2* seg2 = reinterpret_cast<float2*>(out + B);

    uint32_t c001; CVT_BF16X2(c001, 0.01f, 0.01f);

    const int le0 = wid * 32 + g;
    int e[4];
    e[0] = blockIdx.x * NT + le0;
    e[1] = e[0] + 8;
    e[2] = e[0] + 16;
    e[3] = e[0] + 24;
#pragma unroll
    for (int q = 0; q < 4; q++) if (e[q] >= B) e[q] = B - 1;

    float2 ss[4];
#pragma unroll
    for (int q = 0; q < 4; q++) ss[q] = SS2[e[q]];
    float Ks[4] = {0.f, 0.f, 0.f, 0.f};
    float Bs[4] = {0.f, 0.f, 0.f, 0.f};

#pragma unroll 1
    for (int m = 0; m < 8; m++) {
        const float* par = smf + PAR_O + m * 8;
        const float Msv = par[4];
        const float* als = smf + ALS_O + m * ALSP + le0;
        float a[4], lv[4];
        a[0] = als[0]; a[1] = als[8]; a[2] = als[16]; a[3] = als[24];
#pragma unroll
        for (int q = 0; q < 4; q++) lv[q] = ss[q].x * Msv;

        // ---- layer 1 (x = [l, dl, a, 1], b1 folded) ----
        float D[2][4][4];
        {
            uint32_t A0[2][4];
#pragma unroll
            for (int ch = 0; ch < 2; ch++) {
                uint32_t r0 = 0, r1 = 0;
                if (tig == 0) {
                    CVT_BF16X2(r0, lv[ch*2],   ss[ch*2].y   * Msv);
                    CVT_BF16X2(r1, lv[ch*2+1], ss[ch*2+1].y * Msv);
                } else if (tig == 1) {
                    CVT_BF16X2(r0, a[ch*2],   1.0f);
                    CVT_BF16X2(r1, a[ch*2+1], 1.0f);
                }
                A0[ch][0] = r0; A0[ch][1] = r1; A0[ch][2] = 0u; A0[ch][3] = 0u;
            }
#pragma unroll
            for (int t4 = 0; t4 < 4; t4++) {
                uint32_t bb0 = smu[WB_O + widx(m, 0, 0, 0, t4 * 8 + g, tig)];
                uint32_t bb1 = smu[WB_O + widx(m, 0, 0, 1, t4 * 8 + g, tig)];
#pragma unroll
                for (int ch = 0; ch < 2; ch++) {
#pragma unroll
                    for (int i = 0; i < 4; i++) D[ch][t4][i] = 0.0f;
                    mma16816(D[ch][t4], A0[ch], bb0, bb1);
                }
            }
        }

        // ---- transitions l=1 (no bias), l=2 (+b2 bf16): cvt -> bias -> leaky -> mma ----
#pragma unroll 1
        for (int l = 1; l <= 2; l++) {
            uint32_t Ak0[2][4], Ak1[2][4];
#pragma unroll
            for (int t4 = 0; t4 < 4; t4++) {
                uint32_t bias = (l == 2) ? smu[BS2_O + m * 16 + t4 * 4 + tig] : 0u;
#pragma unroll
                for (int ch = 0; ch < 2; ch++) {
                    uint32_t p01, p23, q01, q23;
                    CVT_BF16X2(p01, D[ch][t4][0], D[ch][t4][1]);
                    CVT_BF16X2(p23, D[ch][t4][2], D[ch][t4][3]);
                    if (l == 2) { HADD2(p01, p01, bias); HADD2(p23, p23, bias); }
                    HMUL2(q01, p01, c001); HMAX2(p01, p01, q01);
                    HMUL2(q23, p23, c001); HMAX2(p23, p23, q23);
                    if      (t4 == 0) { Ak0[ch][0] = p01; Ak0[ch][1] = p23; }
                    else if (t4 == 1) { Ak0[ch][2] = p01; Ak0[ch][3] = p23; }
                    else if (t4 == 2) { Ak1[ch][0] = p01; Ak1[ch][1] = p23; }
                    else              { Ak1[ch][2] = p01; Ak1[ch][3] = p23; }
                }
            }
#pragma unroll
            for (int t4 = 0; t4 < 4; t4++) {
                uint32_t b00 = smu[WB_O + widx(m, l, 0, 0, t4 * 8 + g, tig)];
                uint32_t b01 = smu[WB_O + widx(m, l, 0, 1, t4 * 8 + g, tig)];
                uint32_t b10 = smu[WB_O + widx(m, l, 1, 0, t4 * 8 + g, tig)];
                uint32_t b11 = smu[WB_O + widx(m, l, 1, 1, t4 * 8 + g, tig)];
#pragma unroll
                for (int ch = 0; ch < 2; ch++) {
#pragma unroll
                    for (int i = 0; i < 4; i++) D[ch][t4][i] = 0.0f;
                    mma16816(D[ch][t4], Ak0[ch], b00, b01);
                    mma16816(D[ch][t4], Ak1[ch], b10, b11);
                }
            }
        }

        // ---- layer 4 (32->1): quad-local dot (fp32) + quad reduce ----
        float s[4] = {0.f, 0.f, 0.f, 0.f};
        {
            const float* bb = smf + B3_O + m * 32 + cb;
            const float* w4 = smf + W4_O + m * 32 + cb;
#pragma unroll
            for (int t4 = 0; t4 < 4; t4++) {
                float2 bp = *reinterpret_cast<const float2*>(bb + t4 * 8);
                float2 wp = *reinterpret_cast<const float2*>(w4 + t4 * 8);
#pragma unroll
                for (int ch = 0; ch < 2; ch++) {
                    s[ch*2]   = fmaf(leakys(D[ch][t4][0] + bp.x), wp.x, s[ch*2]);
                    s[ch*2]   = fmaf(leakys(D[ch][t4][1] + bp.y), wp.y, s[ch*2]);
                    s[ch*2+1] = fmaf(leakys(D[ch][t4][2] + bp.x), wp.x, s[ch*2+1]);
                    s[ch*2+1] = fmaf(leakys(D[ch][t4][3] + bp.y), wp.y, s[ch*2+1]);
                }
            }
#pragma unroll
            for (int q = 0; q < 4; q++) {
                s[q] += __shfl_xor_sync(0xffffffffu, s[q], 1);
                s[q] += __shfl_xor_sync(0xffffffffu, s[q], 2);
            }
        }
        const float b4v = smf[B4_O + m];
        const float K0v = par[0], K1v = par[1], L0v = par[2], L1v = par[3];
        const float Ms2v = par[5], K1L1v = par[6];
#pragma unroll
        for (int q = 0; q < 4; q++) {
            float nn = NNR * tanh_ap(s[q] + b4v);
            float K = fmaf(a[q], K1v, K0v);
            Ks[q] = fmaf(K, Ms2v, Ks[q]);
            float tL = fmaf(a[q], L1v, L0v) - fabsf(lv[q]);
            float BF = fmaf(a[q] * a[q] * nn, K1L1v, K * tL);
            Bs[q] = fmaf(BF, Msv, Bs[q]);
        }
    }

    // ---- expm epilogue + stores (one lane per quad) ----
    if (tig == 0) {
#pragma unroll
        for (int q = 0; q < 4; q++) {
            float o0, o1;
            finalize(Ks[q], Bs[q], ss[q].x, ss[q].y, Iv, invI, Bv, Kv, o0, o1);
            out[e[q]]  = o0;
            seg2[e[q]] = make_float2(o0, o1);
        }
    }
}

extern "C" void kernel_launch(void* const* d_in, const int* in_sizes, int n_in,
                              void* d_out, int out_size) {
    const float* SS  = (const float*)d_in[0];
    const float* AL  = (const float*)d_in[1];
    const float* K0  = (const float*)d_in[2];
    const float* K1  = (const float*)d_in[3];
    const float* L0  = (const float*)d_in[4];
    const float* L1  = (const float*)d_in[5];
    const float* Ms  = (const float*)d_in[6];
    const float* Ip  = (const float*)d_in[7];
    const float* Bv  = (const float*)d_in[8];
    const float* Kv  = (const float*)d_in[9];
    const float* W1  = (const float*)d_in[10];
    const float* b1  = (const float*)d_in[11];
    const float* W2  = (const float*)d_in[12];
    const float* b2  = (const float*)d_in[13];
    const float* W3  = (const float*)d_in[14];
    const float* b3  = (const float*)d_in[15];
    const float* W4  = (const float*)d_in[16];
    const float* b4  = (const float*)d_in[17];
    float* out = (float*)d_out;

    const int B = in_sizes[0] / 2;
    const int grid = (B + NT - 1) / NT;

    cudaFuncSetAttribute(joint_mma, cudaFuncAttributeMaxDynamicSharedMemorySize, SMEM_BYTES);
    joint_mma<<<grid, NT, SMEM_BYTES>>>(SS, AL, K0, K1, L0, L1, Ms, Ip, Bv, Kv,
                                        W1, b1, W2, b2, W3, b3, W4, b4, out, B);
}

// round 13
// speedup vs baseline: 1.3574x; 1.1794x over previous
#include <cuda_runtime.h>
#include <cuda_bf16.h>
#include <cstdint>
#include <cmath>

#define NT 896                 // 28 warps per CTA
#define EPC 448                // elements per CTA (28 warps * 16)
#define DTC 0.0166667f
#define NNR 0.3f

// ---- smem layout (u32 units) ----
#define WB_O   0               // bf16x2 weight frags: ((((m*3+l)*2+ks)*2+kh)*32+o)*4+tig
#define BS2_O  12288           // bf16x2 b2 pairs [8][16]
#define B3_O   12416           // fp32 [8][32]
#define W4_O   12672           // fp32 [8][32]
#define B4_O   12928           // fp32 [8]
#define PAR_O  12936           // fp32 [8][8]
#define ALS_O  13000           // fp32 [8][449] staged+clipped activations
#define ALSP   449
#define SMEM_U (ALS_O + 8*ALSP)
#define SMEM_BYTES (SMEM_U*4)

__device__ __forceinline__ int widx(int m, int l, int ks, int kh, int o, int tig) {
    return ((((m * 3 + l) * 2 + ks) * 2 + kh) * 32 + o) * 4 + tig;
}

#define CVT_BF16X2(res, a, b) \
    asm("cvt.rn.bf16x2.f32 %0, %1, %2;" : "=r"(res) : "f"(b), "f"(a))
#define HADD2(res, a, b) \
    asm("add.rn.bf16x2 %0, %1, %2;" : "=r"(res) : "r"(a), "r"(b))
#define HMUL2(res, a, b) \
    asm("mul.rn.bf16x2 %0, %1, %2;" : "=r"(res) : "r"(a), "r"(b))
#define HMAX2(res, a, b) \
    asm("max.bf16x2 %0, %1, %2;" : "=r"(res) : "r"(a), "r"(b))

__device__ __forceinline__ void mma16816(float* d, const uint32_t* a, uint32_t b0, uint32_t b1) {
    asm volatile("mma.sync.aligned.m16n8k16.row.col.f32.bf16.bf16.f32 "
                 "{%0,%1,%2,%3}, {%4,%5,%6,%7}, {%8,%9}, {%0,%1,%2,%3};"
                 : "+f"(d[0]), "+f"(d[1]), "+f"(d[2]), "+f"(d[3])
                 : "r"(a[0]), "r"(a[1]), "r"(a[2]), "r"(a[3]), "r"(b0), "r"(b1));
}

__device__ __forceinline__ float tanh_ap(float x) {
    float y; asm("tanh.approx.f32 %0, %1;" : "=f"(y) : "f"(x)); return y;
}
__device__ __forceinline__ float leakys(float x) {
    return fmaxf(x, 0.01f * x);
}

// closed-form 2x2 expm + phi1 solve (validated R1-R11)
__device__ __forceinline__ void finalize(float Ks, float Bs, float s0, float s1,
                                         float Iv, float invI, float Bv, float Kv,
                                         float& o0, float& o1) {
    float A10 = -(Ks + Kv) * invI;
    float Dd  = 2.0f * sqrtf(fmaxf(Ks * Iv, 0.0f));
    float A11 = -(Dd + Bv) * invI;
    float B10 = Bs * invI;
    float a10 = A10 * DTC, a11 = A11 * DTC;
    float s = 0.5f * a11;
    float q = fmaf(s, s, DTC * a10);
    float c, kf;
    if (q >= 0.0f) {
        float w = sqrtf(q);
        c = coshf(w);
        kf = (w > 1e-4f) ? sinhf(w) / w : 1.0f + q * (1.0f / 6.0f);
    } else {
        float w = sqrtf(-q);
        c = __cosf(w);
        kf = (w > 1e-4f) ? __sinf(w) / w : 1.0f + q * (1.0f / 6.0f);
    }
    float es = __expf(s);
    float g  = es * fmaf(-s, kf, c);
    float kk = es * kf;
    float Ad01 = kk * DTC;
    float Ad10 = kk * a10;
    float Ad11 = g + kk * a11;
    float v  = DTC * B10;
    float y1 = kk * v;
    float r1 = (Ad11 - 1.0f) * v;
    float y0 = (r1 - a11 * y1) / a10;
    o0 = fmaf(g,    s0, fmaf(Ad01, s1, y0));
    o1 = fmaf(Ad10, s0, fmaf(Ad11, s1, y1));
}

__global__ __launch_bounds__(NT, 1)
void joint_mma(const float* __restrict__ SS,  const float* __restrict__ AL,
               const float* __restrict__ K0,  const float* __restrict__ K1,
               const float* __restrict__ L0,  const float* __restrict__ L1,
               const float* __restrict__ Ms,  const float* __restrict__ Ip,
               const float* __restrict__ Bvp, const float* __restrict__ Kvp,
               const float* __restrict__ W1,  const float* __restrict__ b1,
               const float* __restrict__ W2,  const float* __restrict__ b2,
               const float* __restrict__ W3,  const float* __restrict__ b3,
               const float* __restrict__ W4,  const float* __restrict__ b4,
               float* __restrict__ out, int B) {
    extern __shared__ uint32_t smu[];
    float* smf = reinterpret_cast<float*>(smu);
    const int tid = threadIdx.x;

    // ---- weight frags (b1 folded into W1 row 3 via x[3]=1) ----
    for (int t = tid; t < 12288; t += NT) {
        int m  = t / 1536;  int r = t - m * 1536;
        int l  = r / 512;   r -= l * 512;
        int ks = r / 256;   r -= ks * 256;
        int kh = r / 128;   r -= kh * 128;
        int o  = r >> 2;    int tg = r & 3;
        int i0 = ks * 16 + kh * 8 + tg * 2;
        float v0 = 0.0f, v1 = 0.0f;
        if (l == 0) {
            if (i0 < 3)      v0 = W1[(m * 32 + o) * 3 + i0];
            if (i0 + 1 < 3)  v1 = W1[(m * 32 + o) * 3 + i0 + 1];
            else if (i0 + 1 == 3) v1 = b1[m * 32 + o];
        } else {
            const float* W = (l == 1) ? W2 : W3;
            v0 = W[(m * 32 + o) * 32 + i0];
            v1 = W[(m * 32 + o) * 32 + i0 + 1];
        }
        uint32_t pk; CVT_BF16X2(pk, v0, v1);
        smu[WB_O + t] = pk;
    }
    for (int t = tid; t < 128; t += NT) {                    // b2 as bf16x2 pairs
        int m = t >> 4, p = t & 15;
        uint32_t pk; CVT_BF16X2(pk, b2[m * 32 + 2 * p], b2[m * 32 + 2 * p + 1]);
        smu[BS2_O + t] = pk;
    }
    for (int t = tid; t < 256; t += NT) {                    // b3, w4 fp32
        smf[B3_O + t] = b3[t];
        smf[W4_O + t] = W4[t];
    }
    if (tid < 8) {
        smf[B4_O + tid] = b4[tid];
        float ms = Ms[tid];
        float* p = smf + PAR_O + tid * 8;
        p[0] = K0[tid]; p[1] = K1[tid]; p[2] = L0[tid]; p[3] = L1[tid];
        p[4] = ms; p[5] = ms * ms; p[6] = K1[tid] * L1[tid];
    }
    // ---- stage AL (coalesced, clipped): EPC elements per CTA ----
    for (int t = tid; t < EPC * 8; t += NT) {
        int le = t >> 3, m = t & 7;
        int ge = blockIdx.x * EPC + le;
        if (ge >= B) ge = B - 1;
        smf[ALS_O + m * ALSP + le] = fminf(fmaxf(AL[(size_t)ge * 8 + m], 0.0f), 1.0f);
    }
    __syncthreads();

    const int lane = tid & 31, wid = tid >> 5;
    const int g = lane >> 2, tig = lane & 3;
    const int cb = 2 * tig;
    const float Iv = __ldg(Ip), Bv = __ldg(Bvp), Kv = __ldg(Kvp);
    const float invI = 1.0f / Iv;
    const float2* SS2 = reinterpret_cast<const float2*>(SS);
    float2* seg2 = reinterpret_cast<float2*>(out + B);

    uint32_t c001; CVT_BF16X2(c001, 0.01f, 0.01f);

    const int le0 = wid * 16 + g;             // local element, [0, EPC)
    int e0 = blockIdx.x * EPC + le0;
    int e1 = e0 + 8;
    if (e0 >= B) e0 = B - 1;
    if (e1 >= B) e1 = B - 1;

    const float2 ss0 = SS2[e0];
    const float2 ss1 = SS2[e1];
    float Ks[2] = {0.f, 0.f};
    float Bs[2] = {0.f, 0.f};

#pragma unroll 1
    for (int m = 0; m < 8; m++) {
        const float* par = smf + PAR_O + m * 8;
        const float Msv = par[4];
        const float* als = smf + ALS_O + m * ALSP + le0;
        float a[2], lv[2];
        a[0] = als[0]; a[1] = als[8];
        lv[0] = ss0.x * Msv; lv[1] = ss1.x * Msv;

        // ---- layer 1 (x = [l, dl, a, 1], b1 folded) ----
        float D[4][4];
        {
            uint32_t A0[4];
            uint32_t r0 = 0, r1 = 0;
            if (tig == 0) {
                CVT_BF16X2(r0, lv[0], ss0.y * Msv);
                CVT_BF16X2(r1, lv[1], ss1.y * Msv);
            } else if (tig == 1) {
                CVT_BF16X2(r0, a[0], 1.0f);
                CVT_BF16X2(r1, a[1], 1.0f);
            }
            A0[0] = r0; A0[1] = r1; A0[2] = 0u; A0[3] = 0u;
#pragma unroll
            for (int t4 = 0; t4 < 4; t4++) {
                uint32_t bb0 = smu[WB_O + widx(m, 0, 0, 0, t4 * 8 + g, tig)];
                uint32_t bb1 = smu[WB_O + widx(m, 0, 0, 1, t4 * 8 + g, tig)];
#pragma unroll
                for (int i = 0; i < 4; i++) D[t4][i] = 0.0f;
                mma16816(D[t4], A0, bb0, bb1);
            }
        }

        // ---- transitions l=1 (no bias), l=2 (+b2 bf16): cvt -> bias -> leaky -> mma ----
#pragma unroll 1
        for (int l = 1; l <= 2; l++) {
            uint32_t Ak0[4], Ak1[4];
#pragma unroll
            for (int t4 = 0; t4 < 4; t4++) {
                uint32_t p01, p23, q01, q23;
                CVT_BF16X2(p01, D[t4][0], D[t4][1]);
                CVT_BF16X2(p23, D[t4][2], D[t4][3]);
                if (l == 2) {
                    uint32_t bias = smu[BS2_O + m * 16 + t4 * 4 + tig];
                    HADD2(p01, p01, bias); HADD2(p23, p23, bias);
                }
                HMUL2(q01, p01, c001); HMAX2(p01, p01, q01);
                HMUL2(q23, p23, c001); HMAX2(p23, p23, q23);
                if      (t4 == 0) { Ak0[0] = p01; Ak0[1] = p23; }
                else if (t4 == 1) { Ak0[2] = p01; Ak0[3] = p23; }
                else if (t4 == 2) { Ak1[0] = p01; Ak1[1] = p23; }
                else              { Ak1[2] = p01; Ak1[3] = p23; }
            }
#pragma unroll
            for (int t4 = 0; t4 < 4; t4++) {
                uint32_t b00 = smu[WB_O + widx(m, l, 0, 0, t4 * 8 + g, tig)];
                uint32_t b01 = smu[WB_O + widx(m, l, 0, 1, t4 * 8 + g, tig)];
                uint32_t b10 = smu[WB_O + widx(m, l, 1, 0, t4 * 8 + g, tig)];
                uint32_t b11 = smu[WB_O + widx(m, l, 1, 1, t4 * 8 + g, tig)];
#pragma unroll
                for (int i = 0; i < 4; i++) D[t4][i] = 0.0f;
                mma16816(D[t4], Ak0, b00, b01);
                mma16816(D[t4], Ak1, b10, b11);
            }
        }

        // ---- layer 4 (32->1): quad-local dot (fp32) + quad reduce ----
        float s0v = 0.f, s1v = 0.f;
        {
            const float* bb = smf + B3_O + m * 32 + cb;
            const float* w4 = smf + W4_O + m * 32 + cb;
#pragma unroll
            for (int t4 = 0; t4 < 4; t4++) {
                float2 bp = *reinterpret_cast<const float2*>(bb + t4 * 8);
                float2 wp = *reinterpret_cast<const float2*>(w4 + t4 * 8);
                s0v = fmaf(leakys(D[t4][0] + bp.x), wp.x, s0v);
                s0v = fmaf(leakys(D[t4][1] + bp.y), wp.y, s0v);
                s1v = fmaf(leakys(D[t4][2] + bp.x), wp.x, s1v);
                s1v = fmaf(leakys(D[t4][3] + bp.y), wp.y, s1v);
            }
            s0v += __shfl_xor_sync(0xffffffffu, s0v, 1);
            s0v += __shfl_xor_sync(0xffffffffu, s0v, 2);
            s1v += __shfl_xor_sync(0xffffffffu, s1v, 1);
            s1v += __shfl_xor_sync(0xffffffffu, s1v, 2);
        }
        const float b4v = smf[B4_O + m];
        const float K0v = par[0], K1v = par[1], L0v = par[2], L1v = par[3];
        const float Ms2v = par[5], K1L1v = par[6];
        float sv[2] = { s0v, s1v };
        float aa[2] = { a[0], a[1] };
#pragma unroll
        for (int q = 0; q < 2; q++) {
            float nn = NNR * tanh_ap(sv[q] + b4v);
            float K = fmaf(aa[q], K1v, K0v);
            Ks[q] = fmaf(K, Ms2v, Ks[q]);
            float tL = fmaf(aa[q], L1v, L0v) - fabsf(lv[q]);
            float BF = fmaf(aa[q] * aa[q] * nn, K1L1v, K * tL);
            Bs[q] = fmaf(BF, Msv, Bs[q]);
        }
    }

    // ---- expm epilogue + stores (one lane per quad) ----
    if (tig == 0) {
        float o0, o1;
        finalize(Ks[0], Bs[0], ss0.x, ss0.y, Iv, invI, Bv, Kv, o0, o1);
        out[e0]  = o0;
        seg2[e0] = make_float2(o0, o1);
        finalize(Ks[1], Bs[1], ss1.x, ss1.y, Iv, invI, Bv, Kv, o0, o1);
        out[e1]  = o0;
        seg2[e1] = make_float2(o0, o1);
    }
}

extern "C" void kernel_launch(void* const* d_in, const int* in_sizes, int n_in,
                              void* d_out, int out_size) {
    const float* SS  = (const float*)d_in[0];
    const float* AL  = (const float*)d_in[1];
    const float* K0  = (const float*)d_in[2];
    const float* K1  = (const float*)d_in[3];
    const float* L0  = (const float*)d_in[4];
    const float* L1  = (const float*)d_in[5];
    const float* Ms  = (const float*)d_in[6];
    const float* Ip  = (const float*)d_in[7];
    const float* Bv  = (const float*)d_in[8];
    const float* Kv  = (const float*)d_in[9];
    const float* W1  = (const float*)d_in[10];
    const float* b1  = (const float*)d_in[11];
    const float* W2  = (const float*)d_in[12];
    const float* b2  = (const float*)d_in[13];
    const float* W3  = (const float*)d_in[14];
    const float* b3  = (const float*)d_in[15];
    const float* W4  = (const float*)d_in[16];
    const float* b4  = (const float*)d_in[17];
    float* out = (float*)d_out;

    const int B = in_sizes[0] / 2;
    const int grid = (B + EPC - 1) / EPC;

    cudaFuncSetAttribute(joint_mma, cudaFuncAttributeMaxDynamicSharedMemorySize, SMEM_BYTES);
    joint_mma<<<grid, NT, SMEM_BYTES>>>(SS, AL, K0, K1, L0, L1, Ms, Ip, Bv, Kv,
                                        W1, b1, W2, b2, W3, b3, W4, b4, out, B);
}

// round 14
// speedup vs baseline: 1.3844x; 1.0199x over previous
#include <cuda_runtime.h>
#include <cuda_bf16.h>
#include <cstdint>
#include <cmath>

#define NT 896                 // 28 warps per CTA
#define EPC 448                // elements per CTA (28 warps * 16)
#define DTC 0.0166667f
#define NNR 0.3f

// ---- smem layout (u32 units) ----
// WB: bf16x2 frags, u32 idx = (((m*3+l)*32 + o)*4 + tig)*4 + j,  j = ks*2+kh
#define WB_O   0
#define BS2_O  12288           // bf16x2 b2 pairs [8][16]
#define C4_O   12416           // float4 [8][4][4]: {b3 pair, w4 pair} per (t4, tig)
#define B4_O   12928           // fp32 [8]
#define PAR_O  12936           // fp32 [8][8]
#define ALS_O  13000           // fp32 [8][449]
#define ALSP   449
#define SMEM_U (ALS_O + 8*ALSP)
#define SMEM_BYTES (SMEM_U*4)

#define CVT_BF16X2(res, a, b) \
    asm("cvt.rn.bf16x2.f32 %0, %1, %2;" : "=r"(res) : "f"(b), "f"(a))
#define HADD2(res, a, b) \
    asm("add.rn.bf16x2 %0, %1, %2;" : "=r"(res) : "r"(a), "r"(b))
#define HMUL2(res, a, b) \
    asm("mul.rn.bf16x2 %0, %1, %2;" : "=r"(res) : "r"(a), "r"(b))
#define HMAX2(res, a, b) \
    asm("max.bf16x2 %0, %1, %2;" : "=r"(res) : "r"(a), "r"(b))

__device__ __forceinline__ void mma16816(float* d, const uint32_t* a, uint32_t b0, uint32_t b1) {
    asm volatile("mma.sync.aligned.m16n8k16.row.col.f32.bf16.bf16.f32 "
                 "{%0,%1,%2,%3}, {%4,%5,%6,%7}, {%8,%9}, {%0,%1,%2,%3};"
                 : "+f"(d[0]), "+f"(d[1]), "+f"(d[2]), "+f"(d[3])
                 : "r"(a[0]), "r"(a[1]), "r"(a[2]), "r"(a[3]), "r"(b0), "r"(b1));
}

__device__ __forceinline__ float tanh_ap(float x) {
    float y; asm("tanh.approx.f32 %0, %1;" : "=f"(y) : "f"(x)); return y;
}
__device__ __forceinline__ float leakys(float x) {
    return fmaxf(x, 0.01f * x);
}

// closed-form 2x2 expm + phi1 solve (validated R1-R13)
__device__ __forceinline__ void finalize(float Ks, float Bs, float s0, float s1,
                                         float Iv, float invI, float Bv, float Kv,
                                         float& o0, float& o1) {
    float A10 = -(Ks + Kv) * invI;
    float Dd  = 2.0f * sqrtf(fmaxf(Ks * Iv, 0.0f));
    float A11 = -(Dd + Bv) * invI;
    float B10 = Bs * invI;
    float a10 = A10 * DTC, a11 = A11 * DTC;
    float s = 0.5f * a11;
    float q = fmaf(s, s, DTC * a10);
    float c, kf;
    if (q >= 0.0f) {
        float w = sqrtf(q);
        c = coshf(w);
        kf = (w > 1e-4f) ? sinhf(w) / w : 1.0f + q * (1.0f / 6.0f);
    } else {
        float w = sqrtf(-q);
        c = __cosf(w);
        kf = (w > 1e-4f) ? __sinf(w) / w : 1.0f + q * (1.0f / 6.0f);
    }
    float es = __expf(s);
    float g  = es * fmaf(-s, kf, c);
    float kk = es * kf;
    float Ad01 = kk * DTC;
    float Ad10 = kk * a10;
    float Ad11 = g + kk * a11;
    float v  = DTC * B10;
    float y1 = kk * v;
    float r1 = (Ad11 - 1.0f) * v;
    float y0 = (r1 - a11 * y1) / a10;
    o0 = fmaf(g,    s0, fmaf(Ad01, s1, y0));
    o1 = fmaf(Ad10, s0, fmaf(Ad11, s1, y1));
}

__global__ __launch_bounds__(NT, 1)
void joint_mma(const float* __restrict__ SS,  const float* __restrict__ AL,
               const float* __restrict__ K0,  const float* __restrict__ K1,
               const float* __restrict__ L0,  const float* __restrict__ L1,
               const float* __restrict__ Ms,  const float* __restrict__ Ip,
               const float* __restrict__ Bvp, const float* __restrict__ Kvp,
               const float* __restrict__ W1,  const float* __restrict__ b1,
               const float* __restrict__ W2,  const float* __restrict__ b2,
               const float* __restrict__ W3,  const float* __restrict__ b3,
               const float* __restrict__ W4,  const float* __restrict__ b4,
               float* __restrict__ out, int B) {
    extern __shared__ uint32_t smu[];
    float* smf = reinterpret_cast<float*>(smu);
    const int tid = threadIdx.x;

    // ---- weight frags: quad-contiguous per (o, tig); b1 folded via x[3]=1 ----
    for (int t = tid; t < 12288; t += NT) {
        int j  = t & 3;
        int tg = (t >> 2) & 3;
        int o  = (t >> 4) & 31;
        int ml = t >> 9;                  // m*3 + l
        int m  = ml / 3, l = ml - m * 3;
        int ks = j >> 1, kh = j & 1;
        int i0 = ks * 16 + kh * 8 + tg * 2;
        float v0 = 0.0f, v1 = 0.0f;
        if (l == 0) {
            if (i0 < 3)      v0 = W1[(m * 32 + o) * 3 + i0];
            if (i0 + 1 < 3)  v1 = W1[(m * 32 + o) * 3 + i0 + 1];
            else if (i0 + 1 == 3) v1 = b1[m * 32 + o];
        } else {
            const float* W = (l == 1) ? W2 : W3;
            v0 = W[(m * 32 + o) * 32 + i0];
            v1 = W[(m * 32 + o) * 32 + i0 + 1];
        }
        uint32_t pk; CVT_BF16X2(pk, v0, v1);
        smu[WB_O + t] = pk;
    }
    for (int t = tid; t < 128; t += NT) {                    // b2 as bf16x2 pairs
        int m = t >> 4, p = t & 15;
        uint32_t pk; CVT_BF16X2(pk, b2[m * 32 + 2 * p], b2[m * 32 + 2 * p + 1]);
        smu[BS2_O + t] = pk;
    }
    for (int t = tid; t < 128; t += NT) {                    // fused {b3 pair, w4 pair}
        int m = t >> 4, r = t & 15, t4 = r >> 2, tg = r & 3;
        int c = t4 * 8 + tg * 2;
        float4 v = make_float4(b3[m * 32 + c], b3[m * 32 + c + 1],
                               W4[m * 32 + c], W4[m * 32 + c + 1]);
        reinterpret_cast<float4*>(smf + C4_O)[t] = v;
    }
    if (tid < 8) {
        smf[B4_O + tid] = b4[tid];
        float ms = Ms[tid];
        float* p = smf + PAR_O + tid * 8;
        p[0] = K0[tid]; p[1] = K1[tid]; p[2] = L0[tid]; p[3] = L1[tid];
        p[4] = ms; p[5] = ms * ms; p[6] = K1[tid] * L1[tid];
    }
    // ---- stage AL (coalesced, clipped) ----
    for (int t = tid; t < EPC * 8; t += NT) {
        int le = t >> 3, m = t & 7;
        int ge = blockIdx.x * EPC + le;
        if (ge >= B) ge = B - 1;
        smf[ALS_O + m * ALSP + le] = fminf(fmaxf(AL[(size_t)ge * 8 + m], 0.0f), 1.0f);
    }
    __syncthreads();

    const int lane = tid & 31, wid = tid >> 5;
    const int g = lane >> 2, tig = lane & 3;
    const float Iv = __ldg(Ip), Bv = __ldg(Bvp), Kv = __ldg(Kvp);
    const float invI = 1.0f / Iv;
    const float2* SS2 = reinterpret_cast<const float2*>(SS);
    float2* seg2 = reinterpret_cast<float2*>(out + B);

    uint32_t c001; CVT_BF16X2(c001, 0.01f, 0.01f);

    const int goff = g * 16 + tig * 4;        // per-thread u32 offset within a layer block
    const uint32_t* wbT = smu + WB_O + goff;  // + m*1536 + l*512 + t4*128
    const float4* c4T = reinterpret_cast<const float4*>(smf + C4_O) + tig;  // + m*16 + t4*4

    const int le0 = wid * 16 + g;
    int e0 = blockIdx.x * EPC + le0;
    int e1 = e0 + 8;
    if (e0 >= B) e0 = B - 1;
    if (e1 >= B) e1 = B - 1;

    const float2 ss0 = SS2[e0];
    const float2 ss1 = SS2[e1];
    float Ks[2] = {0.f, 0.f};
    float Bs[2] = {0.f, 0.f};

#pragma unroll 1
    for (int m = 0; m < 8; m++) {
        const float* par = smf + PAR_O + m * 8;
        const float Msv = par[4];
        const float* als = smf + ALS_O + m * ALSP + le0;
        float a[2], lv[2];
        a[0] = als[0]; a[1] = als[8];
        lv[0] = ss0.x * Msv; lv[1] = ss1.x * Msv;
        const uint32_t* wbM = wbT + m * 1536;

        // ---- layer 1 (x = [l, dl, a, 1], b1 folded): LDS.64 frags ----
        float D[4][4];
        {
            uint32_t A0[4];
            uint32_t r0 = 0, r1 = 0;
            if (tig == 0) {
                CVT_BF16X2(r0, lv[0], ss0.y * Msv);
                CVT_BF16X2(r1, lv[1], ss1.y * Msv);
            } else if (tig == 1) {
                CVT_BF16X2(r0, a[0], 1.0f);
                CVT_BF16X2(r1, a[1], 1.0f);
            }
            A0[0] = r0; A0[1] = r1; A0[2] = 0u; A0[3] = 0u;
#pragma unroll
            for (int t4 = 0; t4 < 4; t4++) {
                uint2 w = *reinterpret_cast<const uint2*>(wbM + t4 * 128);
#pragma unroll
                for (int i = 0; i < 4; i++) D[t4][i] = 0.0f;
                mma16816(D[t4], A0, w.x, w.y);
            }
        }

        // ---- transitions l=1 (no bias), l=2 (+b2): cvt -> leaky -> mma; LDS.128 frags ----
#pragma unroll 1
        for (int l = 1; l <= 2; l++) {
            uint32_t Ak0[4], Ak1[4];
#pragma unroll
            for (int t4 = 0; t4 < 4; t4++) {
                uint32_t p01, p23, q01, q23;
                CVT_BF16X2(p01, D[t4][0], D[t4][1]);
                CVT_BF16X2(p23, D[t4][2], D[t4][3]);
                if (l == 2) {
                    uint32_t bias = smu[BS2_O + m * 16 + t4 * 4 + tig];
                    HADD2(p01, p01, bias); HADD2(p23, p23, bias);
                }
                HMUL2(q01, p01, c001); HMAX2(p01, p01, q01);
                HMUL2(q23, p23, c001); HMAX2(p23, p23, q23);
                if      (t4 == 0) { Ak0[0] = p01; Ak0[1] = p23; }
                else if (t4 == 1) { Ak0[2] = p01; Ak0[3] = p23; }
                else if (t4 == 2) { Ak1[0] = p01; Ak1[1] = p23; }
                else              { Ak1[2] = p01; Ak1[3] = p23; }
            }
            const uint32_t* wbL = wbM + l * 512;
#pragma unroll
            for (int t4 = 0; t4 < 4; t4++) {
                uint4 w = *reinterpret_cast<const uint4*>(wbL + t4 * 128);
#pragma unroll
                for (int i = 0; i < 4; i++) D[t4][i] = 0.0f;
                mma16816(D[t4], Ak0, w.x, w.y);
                mma16816(D[t4], Ak1, w.z, w.w);
            }
        }

        // ---- layer 4 (32->1): fused b3/w4 LDS.128 + quad reduce ----
        float s0v = 0.f, s1v = 0.f;
        {
            const float4* c4 = c4T + m * 16;
#pragma unroll
            for (int t4 = 0; t4 < 4; t4++) {
                float4 cw = c4[t4 * 4];
                s0v = fmaf(leakys(D[t4][0] + cw.x), cw.z, s0v);
                s0v = fmaf(leakys(D[t4][1] + cw.y), cw.w, s0v);
                s1v = fmaf(leakys(D[t4][2] + cw.x), cw.z, s1v);
                s1v = fmaf(leakys(D[t4][3] + cw.y), cw.w, s1v);
            }
            s0v += __shfl_xor_sync(0xffffffffu, s0v, 1);
            s0v += __shfl_xor_sync(0xffffffffu, s0v, 2);
            s1v += __shfl_xor_sync(0xffffffffu, s1v, 1);
            s1v += __shfl_xor_sync(0xffffffffu, s1v, 2);
        }
        const float b4v = smf[B4_O + m];
        const float K0v = par[0], K1v = par[1], L0v = par[2], L1v = par[3];
        const float Ms2v = par[5], K1L1v = par[6];
        float sv[2] = { s0v, s1v };
#pragma unroll
        for (int q = 0; q < 2; q++) {
            float nn = NNR * tanh_ap(sv[q] + b4v);
            float K = fmaf(a[q], K1v, K0v);
            Ks[q] = fmaf(K, Ms2v, Ks[q]);
            float tL = fmaf(a[q], L1v, L0v) - fabsf(lv[q]);
            float BF = fmaf(a[q] * a[q] * nn, K1L1v, K * tL);
            Bs[q] = fmaf(BF, Msv, Bs[q]);
        }
    }

    // ---- expm epilogue + stores (one lane per quad) ----
    if (tig == 0) {
        float o0, o1;
        finalize(Ks[0], Bs[0], ss0.x, ss0.y, Iv, invI, Bv, Kv, o0, o1);
        out[e0]  = o0;
        seg2[e0] = make_float2(o0, o1);
        finalize(Ks[1], Bs[1], ss1.x, ss1.y, Iv, invI, Bv, Kv, o0, o1);
        out[e1]  = o0;
        seg2[e1] = make_float2(o0, o1);
    }
}

extern "C" void kernel_launch(void* const* d_in, const int* in_sizes, int n_in,
                              void* d_out, int out_size) {
    const float* SS  = (const float*)d_in[0];
    const float* AL  = (const float*)d_in[1];
    const float* K0  = (const float*)d_in[2];
    const float* K1  = (const float*)d_in[3];
    const float* L0  = (const float*)d_in[4];
    const float* L1  = (const float*)d_in[5];
    const float* Ms  = (const float*)d_in[6];
    const float* Ip  = (const float*)d_in[7];
    const float* Bv  = (const float*)d_in[8];
    const float* Kv  = (const float*)d_in[9];
    const float* W1  = (const float*)d_in[10];
    const float* b1  = (const float*)d_in[11];
    const float* W2  = (const float*)d_in[12];
    const float* b2  = (const float*)d_in[13];
    const float* W3  = (const float*)d_in[14];
    const float* b3  = (const float*)d_in[15];
    const float* W4  = (const float*)d_in[16];
    const float* b4  = (const float*)d_in[17];
    float* out = (float*)d_out;

    const int B = in_sizes[0] / 2;
    const int grid = (B + EPC - 1) / EPC;

    cudaFuncSetAttribute(joint_mma, cudaFuncAttributeMaxDynamicSharedMemorySize, SMEM_BYTES);
    joint_mma<<<grid, NT, SMEM_BYTES>>>(SS, AL, K0, K1, L0, L1, Ms, Ip, Bv, Kv,
                                        W1, b1, W2, b2, W3, b3, W4, b4, out, B);
}

// round 15
// speedup vs baseline: 1.4878x; 1.0747x over previous
#include <cuda_runtime.h>
#include <cuda_bf16.h>
#include <cstdint>
#include <cmath>

#define NT 896                 // 28 warps per CTA
#define EPC 448                // elements per CTA (28 warps * 16)
#define DTC 0.0166667f
#define NNR 0.3f

// ---- smem layout (u32 units) ----
// WB: bf16x2 frags, u32 idx = (((m*3+l)*32 + o)*4 + tig)*4 + j,  j = ks*2+kh
#define WB_O   0
#define BSB_O  12288           // bf16x2 bias pairs [8][2][16] (b2, b3)
#define W4F_O  12544           // bf16x2 w4 frags [8][4(tig)][4(j)]
#define B4_O   12672           // fp32 [8]
#define PAR_O  12680           // fp32 [8][8]
#define ALS_O  12744           // fp32 [8][449]
#define ALSP   449
#define SMEM_U (ALS_O + 8*ALSP)
#define SMEM_BYTES (SMEM_U*4)

#define CVT_BF16X2(res, a, b) \
    asm("cvt.rn.bf16x2.f32 %0, %1, %2;" : "=r"(res) : "f"(b), "f"(a))
#define HADD2(res, a, b) \
    asm("add.rn.bf16x2 %0, %1, %2;" : "=r"(res) : "r"(a), "r"(b))
#define HMUL2(res, a, b) \
    asm("mul.rn.bf16x2 %0, %1, %2;" : "=r"(res) : "r"(a), "r"(b))
#define HMAX2(res, a, b) \
    asm("max.bf16x2 %0, %1, %2;" : "=r"(res) : "r"(a), "r"(b))

__device__ __forceinline__ void mma16816(float* d, const uint32_t* a, uint32_t b0, uint32_t b1) {
    asm volatile("mma.sync.aligned.m16n8k16.row.col.f32.bf16.bf16.f32 "
                 "{%0,%1,%2,%3}, {%4,%5,%6,%7}, {%8,%9}, {%0,%1,%2,%3};"
                 : "+f"(d[0]), "+f"(d[1]), "+f"(d[2]), "+f"(d[3])
                 : "r"(a[0]), "r"(a[1]), "r"(a[2]), "r"(a[3]), "r"(b0), "r"(b1));
}

__device__ __forceinline__ float tanh_ap(float x) {
    float y; asm("tanh.approx.f32 %0, %1;" : "=f"(y) : "f"(x)); return y;
}

// closed-form 2x2 expm + phi1 solve (validated R1-R14)
__device__ __forceinline__ void finalize(float Ks, float Bs, float s0, float s1,
                                         float Iv, float invI, float Bv, float Kv,
                                         float& o0, float& o1) {
    float A10 = -(Ks + Kv) * invI;
    float Dd  = 2.0f * sqrtf(fmaxf(Ks * Iv, 0.0f));
    float A11 = -(Dd + Bv) * invI;
    float B10 = Bs * invI;
    float a10 = A10 * DTC, a11 = A11 * DTC;
    float s = 0.5f * a11;
    float q = fmaf(s, s, DTC * a10);
    float c, kf;
    if (q >= 0.0f) {
        float w = sqrtf(q);
        c = coshf(w);
        kf = (w > 1e-4f) ? sinhf(w) / w : 1.0f + q * (1.0f / 6.0f);
    } else {
        float w = sqrtf(-q);
        c = __cosf(w);
        kf = (w > 1e-4f) ? __sinf(w) / w : 1.0f + q * (1.0f / 6.0f);
    }
    float es = __expf(s);
    float g  = es * fmaf(-s, kf, c);
    float kk = es * kf;
    float Ad01 = kk * DTC;
    float Ad10 = kk * a10;
    float Ad11 = g + kk * a11;
    float v  = DTC * B10;
    float y1 = kk * v;
    float r1 = (Ad11 - 1.0f) * v;
    float y0 = (r1 - a11 * y1) / a10;
    o0 = fmaf(g,    s0, fmaf(Ad01, s1, y0));
    o1 = fmaf(Ad10, s0, fmaf(Ad11, s1, y1));
}

__global__ __launch_bounds__(NT, 1)
void joint_mma(const float* __restrict__ SS,  const float* __restrict__ AL,
               const float* __restrict__ K0,  const float* __restrict__ K1,
               const float* __restrict__ L0,  const float* __restrict__ L1,
               const float* __restrict__ Ms,  const float* __restrict__ Ip,
               const float* __restrict__ Bvp, const float* __restrict__ Kvp,
               const float* __restrict__ W1,  const float* __restrict__ b1,
               const float* __restrict__ W2,  const float* __restrict__ b2,
               const float* __restrict__ W3,  const float* __restrict__ b3,
               const float* __restrict__ W4,  const float* __restrict__ b4,
               float* __restrict__ out, int B) {
    extern __shared__ uint32_t smu[];
    float* smf = reinterpret_cast<float*>(smu);
    const int tid = threadIdx.x;

    // ---- weight frags: quad-contiguous per (o, tig); b1 folded via x[3]=1 ----
    for (int t = tid; t < 12288; t += NT) {
        int j  = t & 3;
        int tg = (t >> 2) & 3;
        int o  = (t >> 4) & 31;
        int ml = t >> 9;                  // m*3 + l
        int m  = ml / 3, l = ml - m * 3;
        int ks = j >> 1, kh = j & 1;
        int i0 = ks * 16 + kh * 8 + tg * 2;
        float v0 = 0.0f, v1 = 0.0f;
        if (l == 0) {
            if (i0 < 3)      v0 = W1[(m * 32 + o) * 3 + i0];
            if (i0 + 1 < 3)  v1 = W1[(m * 32 + o) * 3 + i0 + 1];
            else if (i0 + 1 == 3) v1 = b1[m * 32 + o];
        } else {
            const float* W = (l == 1) ? W2 : W3;
            v0 = W[(m * 32 + o) * 32 + i0];
            v1 = W[(m * 32 + o) * 32 + i0 + 1];
        }
        uint32_t pk; CVT_BF16X2(pk, v0, v1);
        smu[WB_O + t] = pk;
    }
    for (int t = tid; t < 256; t += NT) {            // b2/b3 as bf16x2 pairs [8][2][16]
        int m = t >> 5, li = (t >> 4) & 1, p = t & 15;
        const float* bp = li ? b3 : b2;
        uint32_t pk; CVT_BF16X2(pk, bp[m * 32 + 2 * p], bp[m * 32 + 2 * p + 1]);
        smu[BSB_O + t] = pk;
    }
    for (int t = tid; t < 128; t += NT) {            // w4 B-frags [8][tig][j]
        int m = t >> 4, tg = (t >> 2) & 3, j = t & 3;
        int ks = j >> 1, kh = j & 1;
        int i0 = ks * 16 + kh * 8 + tg * 2;
        uint32_t pk; CVT_BF16X2(pk, W4[m * 32 + i0], W4[m * 32 + i0 + 1]);
        smu[W4F_O + t] = pk;
    }
    if (tid < 8) {
        smf[B4_O + tid] = b4[tid];
        float ms = Ms[tid];
        float* p = smf + PAR_O + tid * 8;
        p[0] = K0[tid]; p[1] = K1[tid]; p[2] = L0[tid]; p[3] = L1[tid];
        p[4] = ms; p[5] = ms * ms; p[6] = K1[tid] * L1[tid];
    }
    // ---- stage AL (coalesced, clipped) ----
    for (int t = tid; t < EPC * 8; t += NT) {
        int le = t >> 3, m = t & 7;
        int ge = blockIdx.x * EPC + le;
        if (ge >= B) ge = B - 1;
        smf[ALS_O + m * ALSP + le] = fminf(fmaxf(AL[(size_t)ge * 8 + m], 0.0f), 1.0f);
    }
    __syncthreads();

    const int lane = tid & 31, wid = tid >> 5;
    const int g = lane >> 2, tig = lane & 3;
    const float Iv = __ldg(Ip), Bv = __ldg(Bvp), Kv = __ldg(Kvp);
    const float invI = 1.0f / Iv;
    const float2* SS2 = reinterpret_cast<const float2*>(SS);
    float2* seg2 = reinterpret_cast<float2*>(out + B);

    uint32_t c001; CVT_BF16X2(c001, 0.01f, 0.01f);

    const int goff = g * 16 + tig * 4;        // per-thread u32 offset within a layer block
    const uint32_t* wbT = smu + WB_O + goff;  // + m*1536 + l*512 + t4*128

    const int le0 = wid * 16 + g;
    int e0 = blockIdx.x * EPC + le0;
    int e1 = e0 + 8;
    if (e0 >= B) e0 = B - 1;
    if (e1 >= B) e1 = B - 1;

    const float2 ss0 = SS2[e0];
    const float2 ss1 = SS2[e1];
    float Ks[2] = {0.f, 0.f};
    float Bs[2] = {0.f, 0.f};

#pragma unroll 1
    for (int m = 0; m < 8; m++) {
        const float* par = smf + PAR_O + m * 8;
        const float Msv = par[4];
        const float* als = smf + ALS_O + m * ALSP + le0;
        float a[2], lv[2];
        a[0] = als[0]; a[1] = als[8];
        lv[0] = ss0.x * Msv; lv[1] = ss1.x * Msv;
        const uint32_t* wbM = wbT + m * 1536;

        // ---- layer 1 (x = [l, dl, a, 1], b1 folded): LDS.64 frags ----
        float D[4][4];
        {
            uint32_t A0[4];
            uint32_t r0 = 0, r1 = 0;
            if (tig == 0) {
                CVT_BF16X2(r0, lv[0], ss0.y * Msv);
                CVT_BF16X2(r1, lv[1], ss1.y * Msv);
            } else if (tig == 1) {
                CVT_BF16X2(r0, a[0], 1.0f);
                CVT_BF16X2(r1, a[1], 1.0f);
            }
            A0[0] = r0; A0[1] = r1; A0[2] = 0u; A0[3] = 0u;
#pragma unroll
            for (int t4 = 0; t4 < 4; t4++) {
                uint2 w = *reinterpret_cast<const uint2*>(wbM + t4 * 128);
#pragma unroll
                for (int i = 0; i < 4; i++) D[t4][i] = 0.0f;
                mma16816(D[t4], A0, w.x, w.y);
            }
        }

        // ---- transitions l=1 (no bias), l=2 (+b2), l=3 (+b3): cvt -> bias -> leaky ----
        float d4[4];
#pragma unroll 1
        for (int l = 1; l <= 3; l++) {
            uint32_t Ak0[4], Ak1[4];
#pragma unroll
            for (int t4 = 0; t4 < 4; t4++) {
                uint32_t p01, p23, q01, q23;
                CVT_BF16X2(p01, D[t4][0], D[t4][1]);
                CVT_BF16X2(p23, D[t4][2], D[t4][3]);
                if (l >= 2) {
                    uint32_t bias = smu[BSB_O + m * 32 + (l - 2) * 16 + t4 * 4 + tig];
                    HADD2(p01, p01, bias); HADD2(p23, p23, bias);
                }
                HMUL2(q01, p01, c001); HMAX2(p01, p01, q01);
                HMUL2(q23, p23, c001); HMAX2(p23, p23, q23);
                if      (t4 == 0) { Ak0[0] = p01; Ak0[1] = p23; }
                else if (t4 == 1) { Ak0[2] = p01; Ak0[3] = p23; }
                else if (t4 == 2) { Ak1[0] = p01; Ak1[1] = p23; }
                else              { Ak1[2] = p01; Ak1[3] = p23; }
            }
            if (l < 3) {
                const uint32_t* wbL = wbM + l * 512;
#pragma unroll
                for (int t4 = 0; t4 < 4; t4++) {
                    uint4 w = *reinterpret_cast<const uint4*>(wbL + t4 * 128);
#pragma unroll
                    for (int i = 0; i < 4; i++) D[t4][i] = 0.0f;
                    mma16816(D[t4], Ak0, w.x, w.y);
                    mma16816(D[t4], Ak1, w.z, w.w);
                }
            } else {
                // ---- layer 4 via mma: same w4 frag broadcast to all columns;
                //      col 0 (read on tig==0) is the true dot ----
                uint4 w = *reinterpret_cast<const uint4*>(smu + W4F_O + m * 16 + tig * 4);
#pragma unroll
                for (int i = 0; i < 4; i++) d4[i] = 0.0f;
                mma16816(d4, Ak0, w.x, w.y);
                mma16816(d4, Ak1, w.z, w.w);
            }
        }

        // ---- tanh + muscle epilogue (valid on tig==0; other lanes compute garbage, unused) ----
        const float b4v = smf[B4_O + m];
        const float K0v = par[0], K1v = par[1], L0v = par[2], L1v = par[3];
        const float Ms2v = par[5], K1L1v = par[6];
        float sv[2] = { d4[0], d4[2] };
#pragma unroll
        for (int q = 0; q < 2; q++) {
            float nn = NNR * tanh_ap(sv[q] + b4v);
            float K = fmaf(a[q], K1v, K0v);
            Ks[q] = fmaf(K, Ms2v, Ks[q]);
            float tL = fmaf(a[q], L1v, L0v) - fabsf(lv[q]);
            float BF = fmaf(a[q] * a[q] * nn, K1L1v, K * tL);
            Bs[q] = fmaf(BF, Msv, Bs[q]);
        }
    }

    // ---- expm epilogue + stores (one lane per quad) ----
    if (tig == 0) {
        float o0, o1;
        finalize(Ks[0], Bs[0], ss0.x, ss0.y, Iv, invI, Bv, Kv, o0, o1);
        out[e0]  = o0;
        seg2[e0] = make_float2(o0, o1);
        finalize(Ks[1], Bs[1], ss1.x, ss1.y, Iv, invI, Bv, Kv, o0, o1);
        out[e1]  = o0;
        seg2[e1] = make_float2(o0, o1);
    }
}

extern "C" void kernel_launch(void* const* d_in, const int* in_sizes, int n_in,
                              void* d_out, int out_size) {
    const float* SS  = (const float*)d_in[0];
    const float* AL  = (const float*)d_in[1];
    const float* K0  = (const float*)d_in[2];
    const float* K1  = (const float*)d_in[3];
    const float* L0  = (const float*)d_in[4];
    const float* L1  = (const float*)d_in[5];
    const float* Ms  = (const float*)d_in[6];
    const float* Ip  = (const float*)d_in[7];
    const float* Bv  = (const float*)d_in[8];
    const float* Kv  = (const float*)d_in[9];
    const float* W1  = (const float*)d_in[10];
    const float* b1  = (const float*)d_in[11];
    const float* W2  = (const float*)d_in[12];
    const float* b2  = (const float*)d_in[13];
    const float* W3  = (const float*)d_in[14];
    const float* b3  = (const float*)d_in[15];
    const float* W4  = (const float*)d_in[16];
    const float* b4  = (const float*)d_in[17];
    float* out = (float*)d_out;

    const int B = in_sizes[0] / 2;
    const int grid = (B + EPC - 1) / EPC;

    cudaFuncSetAttribute(joint_mma, cudaFuncAttributeMaxDynamicSharedMemorySize, SMEM_BYTES);
    joint_mma<<<grid, NT, SMEM_BYTES>>>(SS, AL, K0, K1, L0, L1, Ms, Ip, Bv, Kv,
                                        W1, b1, W2, b2, W3, b3, W4, b4, out, B);
}